// round 16
// baseline (speedup 1.0000x reference)
#include <cuda_runtime.h>
#include <cuda_fp16.h>
#include <math.h>
#include <stdint.h>

#define HEADS 16
#define DH 64
#define NB 4
#define NSEQ 1024
#define DIMIN 1024
#define BH (NB * HEADS)          // 64
#define MROWS (NB * NSEQ)        // 4096
#define NPROJ 3072
#define PE_PAD 1152
#define QP_LD 1056
#define ATT_SCALE 0.125f

// ---- scratch (device globals; referenced ONLY from device code) ----
__device__ __align__(16) __half g_QPh[(size_t)BH * NSEQ * QP_LD];   // 138 MB
__device__ __align__(16) __half g_xh[(size_t)MROWS * DIMIN];
__device__ __align__(16) __half g_wh[(size_t)NPROJ * DIMIN];    // W^T [n][k]
__device__ __align__(16) __half g_wl[(size_t)NPROJ * DIMIN];
__device__ __align__(16) __half g_qh[(size_t)BH * NSEQ * DH];   // [bh][n][d], hi only
__device__ __align__(16) __half g_kh[(size_t)BH * NSEQ * DH];   // [bh][n][d], hi only
__device__ __align__(16) __half g_vth[(size_t)BH * DH * NSEQ];  // [bh][d][n], hi only
__device__ __align__(16) __half g_peh[(size_t)PE_PAD * DH];
__device__ __align__(16) __half g_pel[(size_t)PE_PAD * DH];

// ============================================================================
// PTX helpers (baseline PTX — safe on plain sm_103 target)
// ============================================================================
__device__ __forceinline__ void mma16816(float* c, const uint32_t* a, const uint32_t* b) {
    asm volatile(
        "mma.sync.aligned.m16n8k16.row.col.f32.f16.f16.f32 "
        "{%0,%1,%2,%3}, {%4,%5,%6,%7}, {%8,%9}, {%0,%1,%2,%3};"
        : "+f"(c[0]), "+f"(c[1]), "+f"(c[2]), "+f"(c[3])
        : "r"(a[0]), "r"(a[1]), "r"(a[2]), "r"(a[3]), "r"(b[0]), "r"(b[1]));
}

__device__ __forceinline__ void ldsm4(uint32_t* r, uint32_t addr) {
    asm volatile("ldmatrix.sync.aligned.m8n8.x4.shared.b16 {%0,%1,%2,%3}, [%4];"
        : "=r"(r[0]), "=r"(r[1]), "=r"(r[2]), "=r"(r[3]) : "r"(addr));
}

__device__ __forceinline__ void cpa16(uint32_t dst, const void* src) {
    asm volatile("cp.async.cg.shared.global [%0], [%1], 16;" :: "r"(dst), "l"(src));
}
__device__ __forceinline__ void cpa_commit() { asm volatile("cp.async.commit_group;"); }
__device__ __forceinline__ void cpa_wait1()  { asm volatile("cp.async.wait_group 1;"); }
__device__ __forceinline__ void cpa_wait0()  { asm volatile("cp.async.wait_group 0;"); }

__device__ __forceinline__ uint32_t pack2(float x, float y) {
    __half2 H = __floats2half2_rn(x, y);
    return *(uint32_t*)&H;
}

// ============================================================================
// conversion kernels
// ============================================================================
__global__ void conv_x(const float* __restrict__ in)
{
    int i = blockIdx.x * 256 + threadIdx.x;
    if (i < MROWS * DIMIN)
        g_xh[i] = __float2half_rn(in[i]);
}

__global__ __launch_bounds__(256)
void conv_wT(const float* __restrict__ Wq, const float* __restrict__ Wkv)
{
    __shared__ float t[32][33];
    int nb = blockIdx.x * 32, kb = blockIdx.y * 32;
    int tx = threadIdx.x & 31, ty = threadIdx.x >> 5;
#pragma unroll
    for (int r = 0; r < 4; r++) {
        int k = kb + ty + r * 8, n = nb + tx;
        float v = (n < 1024) ? Wq[(size_t)k * 1024 + n]
                             : Wkv[(size_t)k * 2048 + (n - 1024)];
        t[ty + r * 8][tx] = v;
    }
    __syncthreads();
#pragma unroll
    for (int r = 0; r < 4; r++) {
        int n = nb + ty + r * 8, k = kb + tx;
        float v = t[tx][ty + r * 8];
        __half h = __float2half_rn(v);
        g_wh[(size_t)n * 1024 + k] = h;
        g_wl[(size_t)n * 1024 + k] = __float2half_rn(v - __half2float(h));
    }
}

__global__ void conv_pe(const float* __restrict__ pe)
{
    int i = blockIdx.x * 256 + threadIdx.x;
    if (i >= PE_PAD * DH) return;
    int p = i >> 6;
    float v = (p < 2 * 512 + 1) ? pe[i] : 0.f;
    __half h = __float2half_rn(v);
    g_peh[i] = h;
    g_pel[i] = __float2half_rn(v - __half2float(h));
}

// ============================================================================
// proj GEMM: 2-product (X rounded to fp16; W split hi/lo).
// C[4096,3072] = Xh @ (Wh + Wl). 512 thr, 16 warps (4x4), 32x32/warp, K-chunk 32.
// ============================================================================
#define LDA 40
#define ARR_E (128 * LDA)              // 5120 elems
#define STAGE_E (3 * ARR_E)            // A, Bh, Bl
#define SMEM_PROJ (2 * STAGE_E * 2)    // 61440 B

__global__ __launch_bounds__(512, 1)
void proj_mma()
{
    extern __shared__ __half sp[];
    const int tid = threadIdx.x;
    const int wid = tid >> 5, lane = tid & 31;
    const int g = lane >> 2, tg = lane & 3;
    const int n0 = blockIdx.x * 128, m0 = blockIdx.y * 128;
    const int wm = (wid >> 2) * 32, wn = (wid & 3) * 32;

    const int lrow = tid >> 2, lcol = (tid & 3) * 8;
    const uint32_t sbase = (uint32_t)__cvta_generic_to_shared(sp);
    const uint32_t ldst = (uint32_t)(lrow * LDA + lcol) * 2;

    float c[2][4][4];
#pragma unroll
    for (int mt = 0; mt < 2; mt++)
#pragma unroll
        for (int nt = 0; nt < 4; nt++)
#pragma unroll
            for (int e = 0; e < 4; e++) c[mt][nt][e] = 0.f;

    {
        size_t offA = (size_t)(m0 + lrow) * DIMIN + lcol;
        size_t offB = (size_t)(n0 + lrow) * DIMIN + lcol;
        uint32_t d = sbase + ldst;
        cpa16(d,                  g_xh + offA);
        cpa16(d + ARR_E * 2,      g_wh + offB);
        cpa16(d + 2 * ARR_E * 2,  g_wl + offB);
        cpa_commit();
    }

    for (int kc = 0; kc < 32; kc++) {
        if (kc < 31) {
            int k0 = (kc + 1) * 32;
            size_t offA = (size_t)(m0 + lrow) * DIMIN + k0 + lcol;
            size_t offB = (size_t)(n0 + lrow) * DIMIN + k0 + lcol;
            uint32_t d = sbase + (uint32_t)(((kc + 1) & 1) * STAGE_E * 2) + ldst;
            cpa16(d,                  g_xh + offA);
            cpa16(d + ARR_E * 2,      g_wh + offB);
            cpa16(d + 2 * ARR_E * 2,  g_wl + offB);
            cpa_commit();
            cpa_wait1();
        } else {
            cpa_wait0();
        }
        __syncthreads();

        const uint32_t st = sbase + (uint32_t)((kc & 1) * STAGE_E * 2);

        uint32_t ah[2][2][4];
#pragma unroll
        for (int mt = 0; mt < 2; mt++)
#pragma unroll
            for (int ks = 0; ks < 2; ks++) {
                uint32_t a = st + (uint32_t)(((wm + mt * 16 + (lane & 15)) * LDA
                                  + ks * 16 + (lane >> 4) * 8) * 2);
                ldsm4(ah[mt][ks], a);
            }
        uint32_t bh[2][2][4], bl[2][2][4];
        {
            int r = lane & 7, j = lane >> 3;
            int rowoff = (j >> 1) * 8 + r;
            int coloff = (j & 1) * 8;
#pragma unroll
            for (int ks = 0; ks < 2; ks++)
#pragma unroll
                for (int np = 0; np < 2; np++) {
                    uint32_t a = st + ARR_E * 2
                               + (uint32_t)(((wn + np * 16 + rowoff) * LDA
                                  + ks * 16 + coloff) * 2);
                    ldsm4(bh[ks][np], a);
                    ldsm4(bl[ks][np], a + ARR_E * 2);
                }
        }
#pragma unroll
        for (int ks = 0; ks < 2; ks++)
#pragma unroll
            for (int mt = 0; mt < 2; mt++)
#pragma unroll
                for (int nt = 0; nt < 4; nt++) {
                    const uint32_t* BH2 = &bh[ks][nt >> 1][(nt & 1) * 2];
                    const uint32_t* BL2 = &bl[ks][nt >> 1][(nt & 1) * 2];
                    mma16816(c[mt][nt], ah[mt][ks], BH2);
                    mma16816(c[mt][nt], ah[mt][ks], BL2);
                }
        __syncthreads();
    }

    // epilogue: Q,K -> fp16 hi only [bh][n][d]; V -> hi-only transposed [bh][d][n]
    const int tgt = n0 >> 10;
    const int nc0 = n0 & 1023;
#pragma unroll
    for (int mt = 0; mt < 2; mt++) {
#pragma unroll
        for (int half = 0; half < 2; half++) {
            int gi = m0 + wm + mt * 16 + g + half * 8;
            int b = gi >> 10, ii = gi & 1023;
#pragma unroll
            for (int nt = 0; nt < 4; nt++) {
                int gc = nc0 + wn + nt * 8 + tg * 2;
                int h = gc >> 6, d = gc & 63;
                int bh_i = b * HEADS + h;
                float v0 = c[mt][nt][half * 2 + 0];
                float v1 = c[mt][nt][half * 2 + 1];
                if (tgt == 0) {
                    size_t oidx = ((size_t)bh_i * NSEQ + ii) * DH + d;
                    *(uint32_t*)(g_qh + oidx) = pack2(v0, v1);
                } else if (tgt == 1) {
                    size_t oidx = ((size_t)bh_i * NSEQ + ii) * DH + d;
                    *(uint32_t*)(g_kh + oidx) = pack2(v0, v1);
                } else {
                    size_t t0 = ((size_t)bh_i * DH + d) * NSEQ + ii;
                    size_t t1 = ((size_t)bh_i * DH + d + 1) * NSEQ + ii;
                    g_vth[t0] = __float2half_rn(v0);
                    g_vth[t1] = __float2half_rn(v1);
                }
            }
        }
    }
}

// ============================================================================
// qp GEMM: 2-product (Q hi only; PE split hi/lo). Output stored fp16.
// ============================================================================
#define LDA2 72
#define TILE_E2 (128 * LDA2)

__global__ __launch_bounds__(256, 2)
void qp_mma()
{
    extern __shared__ __half sm2[];
    __half* Ah = sm2;
    __half* Bh = sm2 + TILE_E2;
    __half* Bl = sm2 + 2 * TILE_E2;

    const int tid = threadIdx.x;
    const int wid = tid >> 5, lane = tid & 31;
    const int g = lane >> 2, tg = lane & 3;
    const int p0 = blockIdx.x * 128, m0 = blockIdx.y * 128;
    const int wm = (wid >> 2) * 64, wn = (wid & 3) * 32;

    float c[4][4][4];
#pragma unroll
    for (int mt = 0; mt < 4; mt++)
#pragma unroll
        for (int nt = 0; nt < 4; nt++)
#pragma unroll
            for (int e = 0; e < 4; e++) c[mt][nt][e] = 0.f;

#pragma unroll
    for (int p = 0; p < 4; p++) {
        int idx = tid + p * 256;
        int row = idx >> 3, unit = idx & 7;
        size_t gA = (size_t)(m0 + row) * DH + unit * 8;
        size_t gB = (size_t)(p0 + row) * DH + unit * 8;
        int so = row * LDA2 + unit * 8;
        *(uint4*)(Ah + so) = *(const uint4*)(g_qh + gA);
        *(uint4*)(Bh + so) = *(const uint4*)(g_peh + gB);
        *(uint4*)(Bl + so) = *(const uint4*)(g_pel + gB);
    }
    __syncthreads();

#pragma unroll
    for (int ks = 0; ks < 4; ks++) {
        const int cb = ks * 16 + tg * 2;
        uint32_t bh[4][2], bl[4][2];
#pragma unroll
        for (int nt = 0; nt < 4; nt++) {
            int n = (wn + nt * 8 + g) * LDA2 + cb;
            bh[nt][0] = *(uint32_t*)(Bh + n);
            bh[nt][1] = *(uint32_t*)(Bh + n + 8);
            bl[nt][0] = *(uint32_t*)(Bl + n);
            bl[nt][1] = *(uint32_t*)(Bl + n + 8);
        }
#pragma unroll
        for (int mt = 0; mt < 4; mt++) {
            int r0 = (wm + mt * 16 + g) * LDA2 + cb;
            int r8 = r0 + 8 * LDA2;
            uint32_t ah[4];
            ah[0] = *(uint32_t*)(Ah + r0);
            ah[1] = *(uint32_t*)(Ah + r8);
            ah[2] = *(uint32_t*)(Ah + r0 + 8);
            ah[3] = *(uint32_t*)(Ah + r8 + 8);
#pragma unroll
            for (int nt = 0; nt < 4; nt++) {
                mma16816(c[mt][nt], ah, bh[nt]);
                mma16816(c[mt][nt], ah, bl[nt]);
            }
        }
    }

#pragma unroll
    for (int mt = 0; mt < 4; mt++) {
#pragma unroll
        for (int half = 0; half < 2; half++) {
            int gi = m0 + wm + mt * 16 + g + half * 8;
            size_t rb = (size_t)gi * QP_LD;
#pragma unroll
            for (int nt = 0; nt < 4; nt++) {
                int pp = p0 + wn + nt * 8 + tg * 2;   // always even
                if (pp + 1 < 1025) {
                    *(uint32_t*)(g_QPh + rb + pp) =
                        pack2(c[mt][nt][half * 2], c[mt][nt][half * 2 + 1]);
                } else if (pp < 1025) {
                    g_QPh[rb + pp] = __float2half_rn(c[mt][nt][half * 2]);
                }
            }
        }
    }
}

// ============================================================================
// attn v6: S = Qh·Kh (1-product), PV = Ph·V (1-product).
// Bias: per-kt coalesced smem staging + ldmatrix seed (bit-identical values).
// ============================================================================
#define ALDK 72
#define ALDV 136
#define LDB 136
#define A_KH 0
#define A_V  18432
#define A_STAGE (18432 + 17408)        // 35840
#define A_BIAS (2 * A_STAGE)           // 71680
#define SMEM_ATTN6 (A_BIAS + 128 * LDB * 2)   // 106496

__device__ __forceinline__ void attn_stage(uint32_t so, size_t base, int bh,
                                           int kt, int tid)
{
#pragma unroll
    for (int p = 0; p < 4; p++) {
        int idx = tid + p * 256;
        int row = idx >> 3, dc = (idx & 7) * 8;
        size_t ga = base + (size_t)(kt * 128 + row) * DH + dc;
        cpa16(so + A_KH + (uint32_t)((row * ALDK + dc) * 2), g_kh + ga);
    }
#pragma unroll
    for (int p = 0; p < 4; p++) {
        int idx = tid + p * 256;
        int dr = idx >> 4, kc = (idx & 15) * 8;
        size_t ga = ((size_t)bh * DH + dr) * NSEQ + kt * 128 + kc;
        cpa16(so + A_V + (uint32_t)((dr * ALDV + kc) * 2), g_vth + ga);
    }
}

__global__ __launch_bounds__(256, 1)
void attn_mma(float* __restrict__ out)
{
    extern __shared__ char sma[];
    const uint32_t sb = (uint32_t)__cvta_generic_to_shared(sma);

    const int tid = threadIdx.x;
    const int wid = tid >> 5, lane = tid & 31;
    const int g = lane >> 2, tg = lane & 3;
    const int bh = blockIdx.x;
    const int qt = blockIdx.y;
    const size_t base = (size_t)bh * NSEQ * DH;
    const int wm = wid * 16;
    const int lr = lane & 7, lj = lane >> 3;
    const int browoff = (lj >> 1) * 8 + lr;
    const int bcoloff = (lj & 1) * 8;

    // ---- stage Q (hi only), extract fragments, then reuse smem ----
    {
        __half* Qh = (__half*)(sma);
#pragma unroll
        for (int p = 0; p < 4; p++) {
            int idx = tid + p * 256;
            int row = idx >> 3, dc = (idx & 7) * 8;
            size_t ga = base + (size_t)(qt * 128 + row) * DH + dc;
            *(uint4*)(Qh + row * ALDK + dc) = *(const uint4*)(g_qh + ga);
        }
        __syncthreads();
    }
    uint32_t qah[4][4];
#pragma unroll
    for (int ks = 0; ks < 4; ks++) {
        uint32_t a = sb + (uint32_t)(((wm + (lane & 15)) * ALDK
                          + ks * 16 + (lane >> 4) * 8) * 2);
        ldsm4(qah[ks], a);
    }
    __syncthreads();

    attn_stage(sb, base, bh, 0, tid);
    cpa_commit();

    const int qi0 = qt * 128 + wm + g;
    const int qi1 = qi0 + 8;

    // bias staging constants (per-thread fixed column)
    const int bcol = tid & 127;
    const int brow0 = tid >> 7;                     // 0 or 1
    const __half* qprow = g_QPh + ((size_t)bh * NSEQ + qt * 128 + brow0) * QP_LD;
    __half* bt = (__half*)(sma + A_BIAS);

    float o[8][4];
#pragma unroll
    for (int nt = 0; nt < 8; nt++)
#pragma unroll
        for (int e = 0; e < 4; e++) o[nt][e] = 0.f;
    float m0r = -INFINITY, m1r = -INFINITY, l0r = 0.f, l1r = 0.f;

    for (int kt = 0; kt < 8; kt++) {
        if (kt < 7) {
            attn_stage(sb + (uint32_t)(((kt + 1) & 1) * A_STAGE), base, bh, kt + 1, tid);
            cpa_commit();
            cpa_wait1();
        } else {
            cpa_wait0();
        }
        __syncthreads();
        const uint32_t st = sb + (uint32_t)((kt & 1) * A_STAGE);

        // ---- stage 128x128 fp16 bias tile (coalesced; clip = clamp) ----
        {
            const int dbase0 = qt * 128 + brow0 - kt * 128 - bcol;
#pragma unroll 16
            for (int p = 0; p < 64; p++) {
                int d = dbase0 + 2 * p;
                int ci = min(max(d, -512), 512) + 512;
                bt[(2 * p + brow0) * LDB + bcol] =
                    qprow[(size_t)(2 * p) * QP_LD + ci];
            }
        }
        __syncthreads();

        // ---- seed accumulators from bias tile via ldmatrix ----
        float c[16][4];
#pragma unroll
        for (int kb = 0; kb < 8; kb++) {
            uint32_t f[4];
            uint32_t a = sb + A_BIAS + (uint32_t)(((wm + (lane & 15)) * LDB
                              + kb * 16 + (lane >> 4) * 8) * 2);
            ldsm4(f, a);
            float2 v0 = __half22float2(*(__half2*)&f[0]);
            float2 v1 = __half22float2(*(__half2*)&f[1]);
            float2 v2 = __half22float2(*(__half2*)&f[2]);
            float2 v3 = __half22float2(*(__half2*)&f[3]);
            c[2 * kb][0] = v0.x;     c[2 * kb][1] = v0.y;
            c[2 * kb][2] = v1.x;     c[2 * kb][3] = v1.y;
            c[2 * kb + 1][0] = v2.x; c[2 * kb + 1][1] = v2.y;
            c[2 * kb + 1][2] = v3.x; c[2 * kb + 1][3] = v3.y;
        }

        // ---- S = bias + Qh Kh^T (1-product) ----
#pragma unroll
        for (int ks = 0; ks < 4; ks++) {
            uint32_t kf[8][4];
#pragma unroll
            for (int np = 0; np < 8; np++) {
                uint32_t a = st + A_KH + (uint32_t)(((np * 16 + browoff) * ALDK
                                  + ks * 16 + bcoloff) * 2);
                ldsm4(kf[np], a);
            }
#pragma unroll
            for (int nt = 0; nt < 16; nt++) {
                const uint32_t* B2 = &kf[nt >> 1][(nt & 1) * 2];
                mma16816(c[nt], qah[ks], B2);
            }
        }

        // ---- scale + register softmax ----
        float mx0 = m0r, mx1 = m1r;
#pragma unroll
        for (int nt = 0; nt < 16; nt++) {
            c[nt][0] *= ATT_SCALE;
            c[nt][1] *= ATT_SCALE;
            c[nt][2] *= ATT_SCALE;
            c[nt][3] *= ATT_SCALE;
            mx0 = fmaxf(mx0, fmaxf(c[nt][0], c[nt][1]));
            mx1 = fmaxf(mx1, fmaxf(c[nt][2], c[nt][3]));
        }
        mx0 = fmaxf(mx0, __shfl_xor_sync(0xffffffff, mx0, 1));
        mx0 = fmaxf(mx0, __shfl_xor_sync(0xffffffff, mx0, 2));
        mx1 = fmaxf(mx1, __shfl_xor_sync(0xffffffff, mx1, 1));
        mx1 = fmaxf(mx1, __shfl_xor_sync(0xffffffff, mx1, 2));

        float rsc0 = __expf(m0r - mx0);
        float rsc1 = __expf(m1r - mx1);
        m0r = mx0; m1r = mx1;

        float sum0 = 0.f, sum1 = 0.f;
#pragma unroll
        for (int nt = 0; nt < 16; nt++) {
            c[nt][0] = __expf(c[nt][0] - mx0);
            c[nt][1] = __expf(c[nt][1] - mx0);
            c[nt][2] = __expf(c[nt][2] - mx1);
            c[nt][3] = __expf(c[nt][3] - mx1);
            sum0 += c[nt][0] + c[nt][1];
            sum1 += c[nt][2] + c[nt][3];
        }
        sum0 += __shfl_xor_sync(0xffffffff, sum0, 1);
        sum0 += __shfl_xor_sync(0xffffffff, sum0, 2);
        sum1 += __shfl_xor_sync(0xffffffff, sum1, 1);
        sum1 += __shfl_xor_sync(0xffffffff, sum1, 2);
        l0r = l0r * rsc0 + sum0;
        l1r = l1r * rsc1 + sum1;

        // ---- O = O*rsc + Ph Vh (1-product) ----
#pragma unroll
        for (int nt = 0; nt < 8; nt++) {
            o[nt][0] *= rsc0; o[nt][1] *= rsc0;
            o[nt][2] *= rsc1; o[nt][3] *= rsc1;
        }
#pragma unroll
        for (int kk = 0; kk < 8; kk++) {
            uint32_t pah[4];
            pah[0] = pack2(c[2 * kk][0],     c[2 * kk][1]);
            pah[1] = pack2(c[2 * kk][2],     c[2 * kk][3]);
            pah[2] = pack2(c[2 * kk + 1][0], c[2 * kk + 1][1]);
            pah[3] = pack2(c[2 * kk + 1][2], c[2 * kk + 1][3]);
            uint32_t vf[4][4];
#pragma unroll
            for (int np = 0; np < 4; np++) {
                uint32_t a = st + A_V + (uint32_t)(((np * 16 + browoff) * ALDV
                                  + kk * 16 + bcoloff) * 2);
                ldsm4(vf[np], a);
            }
#pragma unroll
            for (int nt = 0; nt < 8; nt++) {
                const uint32_t* B2 = &vf[nt >> 1][(nt & 1) * 2];
                mma16816(o[nt], pah, B2);
            }
        }
        __syncthreads();
    }

    // ---- epilogue: O / l ----
    float inv0 = 1.f / l0r, inv1 = 1.f / l1r;
#pragma unroll
    for (int nt = 0; nt < 8; nt++) {
        int d = nt * 8 + tg * 2;
        *(float2*)(out + (base + (size_t)qi0 * DH) + d) =
            make_float2(o[nt][0] * inv0, o[nt][1] * inv0);
        *(float2*)(out + (base + (size_t)qi1 * DH) + d) =
            make_float2(o[nt][2] * inv1, o[nt][3] * inv1);
    }
}

// ============================================================================
// launch
// ============================================================================
extern "C" void kernel_launch(void* const* d_in, const int* in_sizes, int n_in,
                              void* d_out, int out_size)
{
    const float* x   = (const float*)d_in[0];   // [4,1024,1024]
    const float* Wq  = (const float*)d_in[1];   // [1024, 1024]
    const float* Wkv = (const float*)d_in[2];   // [1024, 2048]
    const float* pe  = (const float*)d_in[3];   // [1025, 64]
    float* out = (float*)d_out;                 // [4,16,1024,64]

    conv_x<<<(MROWS * DIMIN + 255) / 256, 256>>>(x);
    conv_wT<<<dim3(NPROJ / 32, DIMIN / 32), 256>>>(Wq, Wkv);
    conv_pe<<<(PE_PAD * DH + 255) / 256, 256>>>(pe);

    cudaFuncSetAttribute(proj_mma, cudaFuncAttributeMaxDynamicSharedMemorySize, SMEM_PROJ);
    proj_mma<<<dim3(NPROJ / 128, MROWS / 128), 512, SMEM_PROJ>>>();

    const int smem_qp = 3 * TILE_E2 * (int)sizeof(__half);    // 55296
    cudaFuncSetAttribute(qp_mma, cudaFuncAttributeMaxDynamicSharedMemorySize, smem_qp);
    qp_mma<<<dim3(9, 512), 256, smem_qp>>>();

    cudaFuncSetAttribute(attn_mma, cudaFuncAttributeMaxDynamicSharedMemorySize, SMEM_ATTN6);
    attn_mma<<<dim3(64, 8), 256, SMEM_ATTN6>>>(out);
}

// round 17
// speedup vs baseline: 1.1265x; 1.1265x over previous
#include <cuda_runtime.h>
#include <cuda_fp16.h>
#include <math.h>
#include <stdint.h>

#define HEADS 16
#define DH 64
#define NB 4
#define NSEQ 1024
#define DIMIN 1024
#define BH (NB * HEADS)          // 64
#define MROWS (NB * NSEQ)        // 4096
#define NPROJ 3072
#define PE_PAD 1152
#define QP_LD 1056
#define ATT_SCALE 0.125f

// ---- scratch (device globals; referenced ONLY from device code) ----
__device__ __align__(16) __half g_QPh[(size_t)BH * NSEQ * QP_LD];   // 138 MB
__device__ __align__(16) __half g_xh[(size_t)MROWS * DIMIN];
__device__ __align__(16) __half g_wh[(size_t)NPROJ * DIMIN];    // W^T [n][k]
__device__ __align__(16) __half g_wl[(size_t)NPROJ * DIMIN];
__device__ __align__(16) __half g_qh[(size_t)BH * NSEQ * DH];   // [bh][n][d], hi only
__device__ __align__(16) __half g_kh[(size_t)BH * NSEQ * DH];   // [bh][n][d], hi only
__device__ __align__(16) __half g_vth[(size_t)BH * DH * NSEQ];  // [bh][d][n], hi only
__device__ __align__(16) __half g_peh[(size_t)PE_PAD * DH];
__device__ __align__(16) __half g_pel[(size_t)PE_PAD * DH];

// ============================================================================
// PTX helpers (baseline PTX — safe on plain sm_103 target)
// ============================================================================
__device__ __forceinline__ void mma16816(float* c, const uint32_t* a, const uint32_t* b) {
    asm volatile(
        "mma.sync.aligned.m16n8k16.row.col.f32.f16.f16.f32 "
        "{%0,%1,%2,%3}, {%4,%5,%6,%7}, {%8,%9}, {%0,%1,%2,%3};"
        : "+f"(c[0]), "+f"(c[1]), "+f"(c[2]), "+f"(c[3])
        : "r"(a[0]), "r"(a[1]), "r"(a[2]), "r"(a[3]), "r"(b[0]), "r"(b[1]));
}

__device__ __forceinline__ void ldsm4(uint32_t* r, uint32_t addr) {
    asm volatile("ldmatrix.sync.aligned.m8n8.x4.shared.b16 {%0,%1,%2,%3}, [%4];"
        : "=r"(r[0]), "=r"(r[1]), "=r"(r[2]), "=r"(r[3]) : "r"(addr));
}

__device__ __forceinline__ void cpa16(uint32_t dst, const void* src) {
    asm volatile("cp.async.cg.shared.global [%0], [%1], 16;" :: "r"(dst), "l"(src));
}
__device__ __forceinline__ void cpa_commit() { asm volatile("cp.async.commit_group;"); }
__device__ __forceinline__ void cpa_wait1()  { asm volatile("cp.async.wait_group 1;"); }
__device__ __forceinline__ void cpa_wait0()  { asm volatile("cp.async.wait_group 0;"); }

__device__ __forceinline__ uint32_t pack2(float x, float y) {
    __half2 H = __floats2half2_rn(x, y);
    return *(uint32_t*)&H;
}

// ============================================================================
// conversion kernels
// ============================================================================
__global__ void conv_x(const float* __restrict__ in)
{
    int i = blockIdx.x * 256 + threadIdx.x;
    if (i < MROWS * DIMIN)
        g_xh[i] = __float2half_rn(in[i]);
}

__global__ __launch_bounds__(256)
void conv_wT(const float* __restrict__ Wq, const float* __restrict__ Wkv)
{
    __shared__ float t[32][33];
    int nb = blockIdx.x * 32, kb = blockIdx.y * 32;
    int tx = threadIdx.x & 31, ty = threadIdx.x >> 5;
#pragma unroll
    for (int r = 0; r < 4; r++) {
        int k = kb + ty + r * 8, n = nb + tx;
        float v = (n < 1024) ? Wq[(size_t)k * 1024 + n]
                             : Wkv[(size_t)k * 2048 + (n - 1024)];
        t[ty + r * 8][tx] = v;
    }
    __syncthreads();
#pragma unroll
    for (int r = 0; r < 4; r++) {
        int n = nb + ty + r * 8, k = kb + tx;
        float v = t[tx][ty + r * 8];
        __half h = __float2half_rn(v);
        g_wh[(size_t)n * 1024 + k] = h;
        g_wl[(size_t)n * 1024 + k] = __float2half_rn(v - __half2float(h));
    }
}

__global__ void conv_pe(const float* __restrict__ pe)
{
    int i = blockIdx.x * 256 + threadIdx.x;
    if (i >= PE_PAD * DH) return;
    int p = i >> 6;
    float v = (p < 2 * 512 + 1) ? pe[i] : 0.f;
    __half h = __float2half_rn(v);
    g_peh[i] = h;
    g_pel[i] = __float2half_rn(v - __half2float(h));
}

// ============================================================================
// proj GEMM: Xh @ (Wh + Wl), except V tiles (tgt==2) use Xh @ Wh only
// (V is consumed hi-only downstream). 512 thr, 16 warps, 32x32/warp.
// ============================================================================
#define LDA 40
#define ARR_E (128 * LDA)              // 5120 elems
#define STAGE_E (3 * ARR_E)            // A, Bh, Bl
#define SMEM_PROJ (2 * STAGE_E * 2)    // 61440 B

__global__ __launch_bounds__(512, 1)
void proj_mma()
{
    extern __shared__ __half sp[];
    const int tid = threadIdx.x;
    const int wid = tid >> 5, lane = tid & 31;
    const int g = lane >> 2, tg = lane & 3;
    const int n0 = blockIdx.x * 128, m0 = blockIdx.y * 128;
    const int wm = (wid >> 2) * 32, wn = (wid & 3) * 32;
    const int tgt = n0 >> 10;                // 0:Q 1:K 2:V
    const bool useBl = (tgt != 2);

    const int lrow = tid >> 2, lcol = (tid & 3) * 8;
    const uint32_t sbase = (uint32_t)__cvta_generic_to_shared(sp);
    const uint32_t ldst = (uint32_t)(lrow * LDA + lcol) * 2;

    float c[2][4][4];
#pragma unroll
    for (int mt = 0; mt < 2; mt++)
#pragma unroll
        for (int nt = 0; nt < 4; nt++)
#pragma unroll
            for (int e = 0; e < 4; e++) c[mt][nt][e] = 0.f;

    {
        size_t offA = (size_t)(m0 + lrow) * DIMIN + lcol;
        size_t offB = (size_t)(n0 + lrow) * DIMIN + lcol;
        uint32_t d = sbase + ldst;
        cpa16(d,              g_xh + offA);
        cpa16(d + ARR_E * 2,  g_wh + offB);
        if (useBl) cpa16(d + 2 * ARR_E * 2, g_wl + offB);
        cpa_commit();
    }

    for (int kc = 0; kc < 32; kc++) {
        if (kc < 31) {
            int k0 = (kc + 1) * 32;
            size_t offA = (size_t)(m0 + lrow) * DIMIN + k0 + lcol;
            size_t offB = (size_t)(n0 + lrow) * DIMIN + k0 + lcol;
            uint32_t d = sbase + (uint32_t)(((kc + 1) & 1) * STAGE_E * 2) + ldst;
            cpa16(d,              g_xh + offA);
            cpa16(d + ARR_E * 2,  g_wh + offB);
            if (useBl) cpa16(d + 2 * ARR_E * 2, g_wl + offB);
            cpa_commit();
            cpa_wait1();
        } else {
            cpa_wait0();
        }
        __syncthreads();

        const uint32_t st = sbase + (uint32_t)((kc & 1) * STAGE_E * 2);

        uint32_t ah[2][2][4];
#pragma unroll
        for (int mt = 0; mt < 2; mt++)
#pragma unroll
            for (int ks = 0; ks < 2; ks++) {
                uint32_t a = st + (uint32_t)(((wm + mt * 16 + (lane & 15)) * LDA
                                  + ks * 16 + (lane >> 4) * 8) * 2);
                ldsm4(ah[mt][ks], a);
            }
        uint32_t bh[2][2][4], bl[2][2][4];
        {
            int r = lane & 7, j = lane >> 3;
            int rowoff = (j >> 1) * 8 + r;
            int coloff = (j & 1) * 8;
#pragma unroll
            for (int ks = 0; ks < 2; ks++)
#pragma unroll
                for (int np = 0; np < 2; np++) {
                    uint32_t a = st + ARR_E * 2
                               + (uint32_t)(((wn + np * 16 + rowoff) * LDA
                                  + ks * 16 + coloff) * 2);
                    ldsm4(bh[ks][np], a);
                    if (useBl) ldsm4(bl[ks][np], a + ARR_E * 2);
                }
        }
#pragma unroll
        for (int ks = 0; ks < 2; ks++)
#pragma unroll
            for (int mt = 0; mt < 2; mt++)
#pragma unroll
                for (int nt = 0; nt < 4; nt++) {
                    const uint32_t* BH2 = &bh[ks][nt >> 1][(nt & 1) * 2];
                    mma16816(c[mt][nt], ah[mt][ks], BH2);
                    if (useBl) {
                        const uint32_t* BL2 = &bl[ks][nt >> 1][(nt & 1) * 2];
                        mma16816(c[mt][nt], ah[mt][ks], BL2);
                    }
                }
        __syncthreads();
    }

    // epilogue: Q,K -> fp16 hi only [bh][n][d]; V -> hi-only transposed [bh][d][n]
    const int nc0 = n0 & 1023;
#pragma unroll
    for (int mt = 0; mt < 2; mt++) {
#pragma unroll
        for (int half = 0; half < 2; half++) {
            int gi = m0 + wm + mt * 16 + g + half * 8;
            int b = gi >> 10, ii = gi & 1023;
#pragma unroll
            for (int nt = 0; nt < 4; nt++) {
                int gc = nc0 + wn + nt * 8 + tg * 2;
                int h = gc >> 6, d = gc & 63;
                int bh_i = b * HEADS + h;
                float v0 = c[mt][nt][half * 2 + 0];
                float v1 = c[mt][nt][half * 2 + 1];
                if (tgt == 0) {
                    size_t oidx = ((size_t)bh_i * NSEQ + ii) * DH + d;
                    *(uint32_t*)(g_qh + oidx) = pack2(v0, v1);
                } else if (tgt == 1) {
                    size_t oidx = ((size_t)bh_i * NSEQ + ii) * DH + d;
                    *(uint32_t*)(g_kh + oidx) = pack2(v0, v1);
                } else {
                    size_t t0 = ((size_t)bh_i * DH + d) * NSEQ + ii;
                    size_t t1 = ((size_t)bh_i * DH + d + 1) * NSEQ + ii;
                    g_vth[t0] = __float2half_rn(v0);
                    g_vth[t1] = __float2half_rn(v1);
                }
            }
        }
    }
}

// ============================================================================
// qp GEMM: 2-product (Q hi only; PE split hi/lo). Output fp16.
// Tile-skip: bias row i only reads p in [max(i-1023,-512), min(i,512)]+512,
// so (row-block, p-tile) pairs outside that window are never consumed.
// ============================================================================
#define LDA2 72
#define TILE_E2 (128 * LDA2)

__global__ __launch_bounds__(256, 2)
void qp_mma()
{
    const int p0 = blockIdx.x * 128, m0 = blockIdx.y * 128;

    // needed-window predicate (uniform per CTA)
    {
        int r0 = m0 & 1023;
        int p_lo = max(r0 - 511, 0);
        int p_hi = min(r0 + 127, 512) + 512;
        if (p0 > p_hi || p0 + 127 < p_lo) return;
    }

    extern __shared__ __half sm2[];
    __half* Ah = sm2;
    __half* Bh = sm2 + TILE_E2;
    __half* Bl = sm2 + 2 * TILE_E2;

    const int tid = threadIdx.x;
    const int wid = tid >> 5, lane = tid & 31;
    const int g = lane >> 2, tg = lane & 3;
    const int wm = (wid >> 2) * 64, wn = (wid & 3) * 32;

    float c[4][4][4];
#pragma unroll
    for (int mt = 0; mt < 4; mt++)
#pragma unroll
        for (int nt = 0; nt < 4; nt++)
#pragma unroll
            for (int e = 0; e < 4; e++) c[mt][nt][e] = 0.f;

#pragma unroll
    for (int p = 0; p < 4; p++) {
        int idx = tid + p * 256;
        int row = idx >> 3, unit = idx & 7;
        size_t gA = (size_t)(m0 + row) * DH + unit * 8;
        size_t gB = (size_t)(p0 + row) * DH + unit * 8;
        int so = row * LDA2 + unit * 8;
        *(uint4*)(Ah + so) = *(const uint4*)(g_qh + gA);
        *(uint4*)(Bh + so) = *(const uint4*)(g_peh + gB);
        *(uint4*)(Bl + so) = *(const uint4*)(g_pel + gB);
    }
    __syncthreads();

#pragma unroll
    for (int ks = 0; ks < 4; ks++) {
        const int cb = ks * 16 + tg * 2;
        uint32_t bh[4][2], bl[4][2];
#pragma unroll
        for (int nt = 0; nt < 4; nt++) {
            int n = (wn + nt * 8 + g) * LDA2 + cb;
            bh[nt][0] = *(uint32_t*)(Bh + n);
            bh[nt][1] = *(uint32_t*)(Bh + n + 8);
            bl[nt][0] = *(uint32_t*)(Bl + n);
            bl[nt][1] = *(uint32_t*)(Bl + n + 8);
        }
#pragma unroll
        for (int mt = 0; mt < 4; mt++) {
            int r0 = (wm + mt * 16 + g) * LDA2 + cb;
            int r8 = r0 + 8 * LDA2;
            uint32_t ah[4];
            ah[0] = *(uint32_t*)(Ah + r0);
            ah[1] = *(uint32_t*)(Ah + r8);
            ah[2] = *(uint32_t*)(Ah + r0 + 8);
            ah[3] = *(uint32_t*)(Ah + r8 + 8);
#pragma unroll
            for (int nt = 0; nt < 4; nt++) {
                mma16816(c[mt][nt], ah, bh[nt]);
                mma16816(c[mt][nt], ah, bl[nt]);
            }
        }
    }

#pragma unroll
    for (int mt = 0; mt < 4; mt++) {
#pragma unroll
        for (int half = 0; half < 2; half++) {
            int gi = m0 + wm + mt * 16 + g + half * 8;
            size_t rb = (size_t)gi * QP_LD;
#pragma unroll
            for (int nt = 0; nt < 4; nt++) {
                int pp = p0 + wn + nt * 8 + tg * 2;   // always even
                if (pp + 1 < 1025) {
                    *(uint32_t*)(g_QPh + rb + pp) =
                        pack2(c[mt][nt][half * 2], c[mt][nt][half * 2 + 1]);
                } else if (pp < 1025) {
                    g_QPh[rb + pp] = __float2half_rn(c[mt][nt][half * 2]);
                }
            }
        }
    }
}

// ============================================================================
// attn (R14 version, reverted): S = Qh·Kh (1-product), PV = Ph·V (1-product).
// cp.async 2-stage K/V prefetch, ldmatrix feeds, fp16 direct-global bias seed.
// ============================================================================
#define ALDK 72
#define ALDV 136
#define A_KH 0
#define A_V  18432
#define A_STAGE (18432 + 17408)    // 35840
#define SMEM_ATTN5 (2 * A_STAGE)   // 71680

__device__ __forceinline__ void attn_stage(uint32_t so, size_t base, int bh,
                                           int kt, int tid)
{
#pragma unroll
    for (int p = 0; p < 4; p++) {
        int idx = tid + p * 256;
        int row = idx >> 3, dc = (idx & 7) * 8;
        size_t ga = base + (size_t)(kt * 128 + row) * DH + dc;
        cpa16(so + A_KH + (uint32_t)((row * ALDK + dc) * 2), g_kh + ga);
    }
#pragma unroll
    for (int p = 0; p < 4; p++) {
        int idx = tid + p * 256;
        int dr = idx >> 4, kc = (idx & 15) * 8;
        size_t ga = ((size_t)bh * DH + dr) * NSEQ + kt * 128 + kc;
        cpa16(so + A_V + (uint32_t)((dr * ALDV + kc) * 2), g_vth + ga);
    }
}

__global__ __launch_bounds__(256, 1)
void attn_mma(float* __restrict__ out)
{
    extern __shared__ char sma[];
    const uint32_t sb = (uint32_t)__cvta_generic_to_shared(sma);

    const int tid = threadIdx.x;
    const int wid = tid >> 5, lane = tid & 31;
    const int g = lane >> 2, tg = lane & 3;
    const int bh = blockIdx.x;
    const int qt = blockIdx.y;
    const size_t base = (size_t)bh * NSEQ * DH;
    const int wm = wid * 16;
    const int lr = lane & 7, lj = lane >> 3;
    const int browoff = (lj >> 1) * 8 + lr;
    const int bcoloff = (lj & 1) * 8;

    // ---- stage Q (hi only), extract fragments, then reuse smem ----
    {
        __half* Qh = (__half*)(sma);
#pragma unroll
        for (int p = 0; p < 4; p++) {
            int idx = tid + p * 256;
            int row = idx >> 3, dc = (idx & 7) * 8;
            size_t ga = base + (size_t)(qt * 128 + row) * DH + dc;
            *(uint4*)(Qh + row * ALDK + dc) = *(const uint4*)(g_qh + ga);
        }
        __syncthreads();
    }
    uint32_t qah[4][4];
#pragma unroll
    for (int ks = 0; ks < 4; ks++) {
        uint32_t a = sb + (uint32_t)(((wm + (lane & 15)) * ALDK
                          + ks * 16 + (lane >> 4) * 8) * 2);
        ldsm4(qah[ks], a);
    }
    __syncthreads();

    attn_stage(sb, base, bh, 0, tid);
    cpa_commit();

    const int qi0 = qt * 128 + wm + g;
    const int qi1 = qi0 + 8;
    const __half* r0 = g_QPh + ((size_t)bh * NSEQ + qi0) * QP_LD + 512;
    const __half* r1 = g_QPh + ((size_t)bh * NSEQ + qi1) * QP_LD + 512;

    float o[8][4];
#pragma unroll
    for (int nt = 0; nt < 8; nt++)
#pragma unroll
        for (int e = 0; e < 4; e++) o[nt][e] = 0.f;
    float m0r = -INFINITY, m1r = -INFINITY, l0r = 0.f, l1r = 0.f;

    for (int kt = 0; kt < 8; kt++) {
        if (kt < 7) {
            attn_stage(sb + (uint32_t)(((kt + 1) & 1) * A_STAGE), base, bh, kt + 1, tid);
            cpa_commit();
            cpa_wait1();
        } else {
            cpa_wait0();
        }
        __syncthreads();
        const uint32_t st = sb + (uint32_t)((kt & 1) * A_STAGE);

        // ---- seed accumulators with bias (fp16 direct-global gather) ----
        float c[16][4];
        const int dbase = qi0 - kt * 128 - tg * 2;
#pragma unroll
        for (int nt = 0; nt < 16; nt++) {
            int d0 = dbase - nt * 8;
            int iA = min(max(d0,     -512), 512);
            int iB = min(max(d0 - 1, -512), 512);
            int iC = min(max(d0 + 8, -512), 512);
            int iD = min(max(d0 + 7, -512), 512);
            c[nt][0] = __half2float(r0[iA]);
            c[nt][1] = __half2float(r0[iB]);
            c[nt][2] = __half2float(r1[iC]);
            c[nt][3] = __half2float(r1[iD]);
        }

        // ---- S = bias + Qh Kh^T (1-product) ----
#pragma unroll
        for (int ks = 0; ks < 4; ks++) {
            uint32_t kf[8][4];
#pragma unroll
            for (int np = 0; np < 8; np++) {
                uint32_t a = st + A_KH + (uint32_t)(((np * 16 + browoff) * ALDK
                                  + ks * 16 + bcoloff) * 2);
                ldsm4(kf[np], a);
            }
#pragma unroll
            for (int nt = 0; nt < 16; nt++) {
                const uint32_t* B2 = &kf[nt >> 1][(nt & 1) * 2];
                mma16816(c[nt], qah[ks], B2);
            }
        }

        // ---- scale + register softmax ----
        float mx0 = m0r, mx1 = m1r;
#pragma unroll
        for (int nt = 0; nt < 16; nt++) {
            c[nt][0] *= ATT_SCALE;
            c[nt][1] *= ATT_SCALE;
            c[nt][2] *= ATT_SCALE;
            c[nt][3] *= ATT_SCALE;
            mx0 = fmaxf(mx0, fmaxf(c[nt][0], c[nt][1]));
            mx1 = fmaxf(mx1, fmaxf(c[nt][2], c[nt][3]));
        }
        mx0 = fmaxf(mx0, __shfl_xor_sync(0xffffffff, mx0, 1));
        mx0 = fmaxf(mx0, __shfl_xor_sync(0xffffffff, mx0, 2));
        mx1 = fmaxf(mx1, __shfl_xor_sync(0xffffffff, mx1, 1));
        mx1 = fmaxf(mx1, __shfl_xor_sync(0xffffffff, mx1, 2));

        float rsc0 = __expf(m0r - mx0);
        float rsc1 = __expf(m1r - mx1);
        m0r = mx0; m1r = mx1;

        float sum0 = 0.f, sum1 = 0.f;
#pragma unroll
        for (int nt = 0; nt < 16; nt++) {
            c[nt][0] = __expf(c[nt][0] - mx0);
            c[nt][1] = __expf(c[nt][1] - mx0);
            c[nt][2] = __expf(c[nt][2] - mx1);
            c[nt][3] = __expf(c[nt][3] - mx1);
            sum0 += c[nt][0] + c[nt][1];
            sum1 += c[nt][2] + c[nt][3];
        }
        sum0 += __shfl_xor_sync(0xffffffff, sum0, 1);
        sum0 += __shfl_xor_sync(0xffffffff, sum0, 2);
        sum1 += __shfl_xor_sync(0xffffffff, sum1, 1);
        sum1 += __shfl_xor_sync(0xffffffff, sum1, 2);
        l0r = l0r * rsc0 + sum0;
        l1r = l1r * rsc1 + sum1;

        // ---- O = O*rsc + Ph Vh (1-product) ----
#pragma unroll
        for (int nt = 0; nt < 8; nt++) {
            o[nt][0] *= rsc0; o[nt][1] *= rsc0;
            o[nt][2] *= rsc1; o[nt][3] *= rsc1;
        }
#pragma unroll
        for (int kk = 0; kk < 8; kk++) {
            uint32_t pah[4];
            pah[0] = pack2(c[2 * kk][0],     c[2 * kk][1]);
            pah[1] = pack2(c[2 * kk][2],     c[2 * kk][3]);
            pah[2] = pack2(c[2 * kk + 1][0], c[2 * kk + 1][1]);
            pah[3] = pack2(c[2 * kk + 1][2], c[2 * kk + 1][3]);
            uint32_t vf[4][4];
#pragma unroll
            for (int np = 0; np < 4; np++) {
                uint32_t a = st + A_V + (uint32_t)(((np * 16 + browoff) * ALDV
                                  + kk * 16 + bcoloff) * 2);
                ldsm4(vf[np], a);
            }
#pragma unroll
            for (int nt = 0; nt < 8; nt++) {
                const uint32_t* B2 = &vf[nt >> 1][(nt & 1) * 2];
                mma16816(o[nt], pah, B2);
            }
        }
        __syncthreads();
    }

    // ---- epilogue: O / l ----
    float inv0 = 1.f / l0r, inv1 = 1.f / l1r;
#pragma unroll
    for (int nt = 0; nt < 8; nt++) {
        int d = nt * 8 + tg * 2;
        *(float2*)(out + (base + (size_t)qi0 * DH) + d) =
            make_float2(o[nt][0] * inv0, o[nt][1] * inv0);
        *(float2*)(out + (base + (size_t)qi1 * DH) + d) =
            make_float2(o[nt][2] * inv1, o[nt][3] * inv1);
    }
}

// ============================================================================
// launch
// ============================================================================
extern "C" void kernel_launch(void* const* d_in, const int* in_sizes, int n_in,
                              void* d_out, int out_size)
{
    const float* x   = (const float*)d_in[0];   // [4,1024,1024]
    const float* Wq  = (const float*)d_in[1];   // [1024, 1024]
    const float* Wkv = (const float*)d_in[2];   // [1024, 2048]
    const float* pe  = (const float*)d_in[3];   // [1025, 64]
    float* out = (float*)d_out;                 // [4,16,1024,64]

    conv_x<<<(MROWS * DIMIN + 255) / 256, 256>>>(x);
    conv_wT<<<dim3(NPROJ / 32, DIMIN / 32), 256>>>(Wq, Wkv);
    conv_pe<<<(PE_PAD * DH + 255) / 256, 256>>>(pe);

    cudaFuncSetAttribute(proj_mma, cudaFuncAttributeMaxDynamicSharedMemorySize, SMEM_PROJ);
    proj_mma<<<dim3(NPROJ / 128, MROWS / 128), 512, SMEM_PROJ>>>();

    const int smem_qp = 3 * TILE_E2 * (int)sizeof(__half);    // 55296
    cudaFuncSetAttribute(qp_mma, cudaFuncAttributeMaxDynamicSharedMemorySize, smem_qp);
    qp_mma<<<dim3(9, 512), 256, smem_qp>>>();

    cudaFuncSetAttribute(attn_mma, cudaFuncAttributeMaxDynamicSharedMemorySize, SMEM_ATTN5);
    attn_mma<<<dim3(64, 8), 256, SMEM_ATTN5>>>(out);
}